// round 1
// baseline (speedup 1.0000x reference)
#include <cuda_runtime.h>
#include <cuda_bf16.h>

// TD loss: backward recurrence over T=256 per column, B columns independent.
// Memory-bound: 7 input streams + 1 output stream, all coalesced.

#ifndef TD_T
#define TD_T 256
#endif
#define TD_GAMMA 0.99f

__global__ void __launch_bounds__(256) td_loss_kernel(
    const float* __restrict__ reward,
    const float* __restrict__ discount,
    const float* __restrict__ value,
    const float* __restrict__ target_value,
    const int*   __restrict__ step_type,
    const int*   __restrict__ rollout_b,
    const int*   __restrict__ train_b,
    float*       __restrict__ out,
    int B)
{
    const int b = blockIdx.x * blockDim.x + threadIdx.x;
    if (b >= B) return;

    const long long stride = B;
    long long base = (long long)(TD_T - 1) * stride + b;

    // acc starts at target_value[T-1]; last loss row is zero.
    float acc = target_value[base];
    out[base] = 0.0f;

    // t = T-2 .. 0. All loads independent of acc -> compiler pipelines them.
    #pragma unroll 4
    for (int t = TD_T - 2; t >= 0; --t) {
        const long long i  = (long long)t * stride + b;  // row t
        const long long i1 = i + stride;                 // row t+1

        const float d  = discount[i1] * TD_GAMMA;
        const float r  = reward[i1];
        const int   st = step_type[i];
        const int   rb = rollout_b[i];
        const int   tb = train_b[i];
        const float tv = target_value[i];
        const float vl = value[i];

        // is_last[t]; b-mask forced False at t==0 (b.at[0].set(False))
        const bool l = (st == 2) || ((t != 0) && ((rb | tb) != 0));

        const float ret = fmaf(acc, d, r);   // returns[t]
        acc = l ? tv : ret;                  // exact: l in {0,1}

        const float diff = ret - vl;
        out[i] = diff * diff;
    }
}

extern "C" void kernel_launch(void* const* d_in, const int* in_sizes, int n_in,
                              void* d_out, int out_size)
{
    const float* reward       = (const float*)d_in[0];
    const float* discount     = (const float*)d_in[1];
    const float* value        = (const float*)d_in[2];
    const float* target_value = (const float*)d_in[3];
    const int*   step_type    = (const int*)d_in[4];
    const int*   rollout_b    = (const int*)d_in[5];
    const int*   train_b      = (const int*)d_in[6];
    float*       out          = (float*)d_out;

    const int B = in_sizes[0] / TD_T;   // (T, B) row-major, T = 256

    const int threads = 256;
    const int blocks  = (B + threads - 1) / threads;
    td_loss_kernel<<<blocks, threads>>>(reward, discount, value, target_value,
                                        step_type, rollout_b, train_b, out, B);
}